// round 14
// baseline (speedup 1.0000x reference)
#include <cuda_runtime.h>

// Net_2095944040841: 3-layer LSTM (reference's buggy c-state wiring) on GB300.
// R12: 13 gate warps (quarter-split) + WARP-TILED weight layout: each
// (gate,chunk) is a 256B contiguous span per warp -> guaranteed 2-wavefront
// weight loads (fixes R11's bank conflicts). Single-homed state buffers with
// per-quarter pointer select; x single-buffered. 2 barriers/step (R10 pipeline).

#define T_LEN 1024
#define IN_D  20
#define HIDN  50
#define OUT_D 8
#define NB    4
#define NCTA  128
#define NTH   448

// shared memory layout (float offsets)
#define WPA_OFF 0            // cell1: 12 ug x 1280 + half ug 640 = 16,000
#define WPB_OFF 16000        // cell2: 12 x 1792 + 896          = 22,400
#define WPC_OFF 38400        // cell3: 12 x 1344 + 672          = 16,800
#define W2_OFF  55200        // 8 x 50 = 400
#define X_OFF   55600        // 80 (single buffer)
#define H1_OFF  55680        // 2 x 240 (parity), base % 32 == 0
#define H2_OFF  56168        // 2 x 240, base % 32 == 8
#define H3_OFF  56672        // 2 x 240, base % 32 == 0
#define SMEM_FLT 57152       // 228,608 bytes

typedef unsigned long long ull;

static __device__ __forceinline__ void upk(ull v, float &a, float &b) {
    asm("mov.b64 {%0,%1}, %2;" : "=f"(a), "=f"(b) : "l"(v));
}
static __device__ __forceinline__ ull fma2(ull a, ull b, ull c) {
    ull d; asm("fma.rn.f32x2 %0, %1, %2, %3;" : "=l"(d) : "l"(a), "l"(b), "l"(c)); return d;
}
static __device__ __forceinline__ ull add2(ull a, ull b) {
    ull d; asm("add.rn.f32x2 %0, %1, %2;" : "=l"(d) : "l"(a), "l"(b)); return d;
}
static __device__ __forceinline__ float tanhap(float x) {
    float t; asm("tanh.approx.f32 %0, %1;" : "=f"(t) : "f"(x)); return t;
}
static __device__ __forceinline__ float sigm(float x) {
    return fmaf(tanhap(0.5f * x), 0.5f, 0.5f);
}

struct Acc8 { ull i0, i1, f0, f1, g0, g1, o0, o1; };

// Quarter-GEMV, warp-tiled weights: per chunk each gate pointer reads ONE 16B
// block; pointers advance by ws (64 full-warp / 32 half-warp) per chunk.
template<int NQ, bool HASF>
static __device__ __forceinline__ void gemv_q(
    const float* wi, const float* wf, const float* wg, const float* wo,
    int ws, const float* __restrict__ inp, Acc8 &A)
{
#pragma unroll
    for (int kk = 0; kk < NQ; kk++) {
        ulonglong2 qa = *reinterpret_cast<const ulonglong2*>(inp + 16 * kk);
        ulonglong2 qb = *reinterpret_cast<const ulonglong2*>(inp + 16 * kk + 8);
        ulonglong2 wI = *reinterpret_cast<const ulonglong2*>(wi);
        ulonglong2 wG = *reinterpret_cast<const ulonglong2*>(wg);
        ulonglong2 wO = *reinterpret_cast<const ulonglong2*>(wo);
        wi += ws; wg += ws; wo += ws;
        A.i0 = fma2(wI.x, qa.x, A.i0); A.i1 = fma2(wI.x, qa.y, A.i1);
        A.i0 = fma2(wI.y, qb.x, A.i0); A.i1 = fma2(wI.y, qb.y, A.i1);
        A.g0 = fma2(wG.x, qa.x, A.g0); A.g1 = fma2(wG.x, qa.y, A.g1);
        A.g0 = fma2(wG.y, qb.x, A.g0); A.g1 = fma2(wG.y, qb.y, A.g1);
        A.o0 = fma2(wO.x, qa.x, A.o0); A.o1 = fma2(wO.x, qa.y, A.o1);
        A.o0 = fma2(wO.y, qb.x, A.o0); A.o1 = fma2(wO.y, qb.y, A.o1);
        if (HASF) {
            ulonglong2 wF = *reinterpret_cast<const ulonglong2*>(wf);
            wf += ws;
            A.f0 = fma2(wF.x, qa.x, A.f0); A.f1 = fma2(wF.x, qa.y, A.f1);
            A.f0 = fma2(wF.y, qb.x, A.f0); A.f1 = fma2(wF.y, qb.y, A.f1);
        }
    }
}

// combine quarters: lane bits 3 (xor8) and 4 (xor16)
#define CMB(a) { ull _o = __shfl_xor_sync(0xffffffffu, a, 8);  a = add2(a, _o); \
                 _o = __shfl_xor_sync(0xffffffffu, a, 16);     a = add2(a, _o); }
#define CMB4(A) { CMB(A.i0) CMB(A.i1) CMB(A.f0) CMB(A.f1) CMB(A.g0) CMB(A.g1) CMB(A.o0) CMB(A.o1) }
#define CMB3(A) { CMB(A.i0) CMB(A.i1) CMB(A.g0) CMB(A.g1) CMB(A.o0) CMB(A.o1) }

extern __shared__ float sm[];

__global__ void __launch_bounds__(NTH, 1)
lstm_persist_kernel(const float* __restrict__ x,
                    const float* __restrict__ W1,   const float* __restrict__ b1,
                    const float* __restrict__ Wih1, const float* __restrict__ Whh1,
                    const float* __restrict__ bih1, const float* __restrict__ bhh1,
                    const float* __restrict__ Wih2, const float* __restrict__ Whh2,
                    const float* __restrict__ bih2, const float* __restrict__ bhh2,
                    const float* __restrict__ Wih3, const float* __restrict__ Whh3,
                    const float* __restrict__ bih3, const float* __restrict__ bhh3,
                    const float* __restrict__ W2,   const float* __restrict__ b2,
                    float* __restrict__ out)
{
    const int tid = threadIdx.x;
    const int b0  = blockIdx.x * NB;

    // ---------------- init ----------------
    // stage W1 (1000) and fused-x Wc (200x20=4000) inside not-yet-filled WPB
    for (int i = tid; i < HIDN * IN_D; i += NTH) sm[WPB_OFF + i] = W1[i];
    __syncthreads();
    for (int i = tid; i < 200 * IN_D; i += NTH) {
        int r = i / IN_D, k = i % IN_D;
        float acc = 0.f;
#pragma unroll 10
        for (int j = 0; j < HIDN; j++)
            acc += Wih1[r * HIDN + j] * sm[WPB_OFF + j * IN_D + k];
        sm[WPB_OFF + 1000 + i] = acc;   // Wc[r][k]
    }
    __syncthreads();

    // fill cell1 physical (reads Wc scratch + Whh1)
    for (int i = tid; i < 50 * 4 * 80; i += NTH) {
        int u = i / 320, rem = i % 320;
        int g = rem / 80, col = rem % 80;
        int qd = col / 20, cc = col % 20, kk = cc / 4, j = cc % 4;
        int r = g * 50 + u;
        float v = 0.f;
        if (col < 20) v = sm[WPB_OFF + 1000 + r * IN_D + col];
        else { int hi_ = col - 20; if (hi_ < HIDN) v = Whh1[r * HIDN + hi_]; }
        int phys;
        if (u < 48) phys = (u >> 2) * 1280 + g * 320 + kk * 64 + ((u & 3) * 4 + qd) * 4 + j;
        else        phys = 15360 + g * 160 + kk * 32 + ((u - 48) * 4 + qd) * 4 + j;
        sm[WPA_OFF + phys] = v;
    }
    __syncthreads();   // scratch reads complete before WPB fill

    // fill cell2 physical
    for (int i = tid; i < 50 * 4 * 112; i += NTH) {
        int u = i / 448, rem = i % 448;
        int g = rem / 112, col = rem % 112;
        int qd = col / 28, cc = col % 28, kk = cc / 4, j = cc % 4;
        int r = g * 50 + u;
        float v = 0.f;
        if (qd < 2) { if (col < HIDN) v = Wih2[r * HIDN + col]; }
        else { int hi_ = col - 56; if (hi_ >= 0 && hi_ < HIDN) v = Whh2[r * HIDN + hi_]; }
        int phys;
        if (u < 48) phys = (u >> 2) * 1792 + g * 448 + kk * 64 + ((u & 3) * 4 + qd) * 4 + j;
        else        phys = 21504 + g * 224 + kk * 32 + ((u - 48) * 4 + qd) * 4 + j;
        sm[WPB_OFF + phys] = v;
    }
    // fill cell3 physical (gates i, g, o -> source rows u, 100+u, 150+u)
    for (int i = tid; i < 50 * 3 * 112; i += NTH) {
        int u = i / 336, rem = i % 336;
        int g3 = rem / 112, col = rem % 112;
        int qd = col / 28, cc = col % 28, kk = cc / 4, j = cc % 4;
        int r = (g3 == 0) ? u : (g3 == 1 ? 100 + u : 150 + u);
        float v = 0.f;
        if (qd < 2) { if (col < HIDN) v = Wih3[r * HIDN + col]; }
        else { int hi_ = col - 56; if (hi_ >= 0 && hi_ < HIDN) v = Whh3[r * HIDN + hi_]; }
        int phys;
        if (u < 48) phys = (u >> 2) * 1344 + g3 * 448 + kk * 64 + ((u & 3) * 4 + qd) * 4 + j;
        else        phys = 16128 + g3 * 224 + kk * 32 + ((u - 48) * 4 + qd) * 4 + j;
        sm[WPC_OFF + phys] = v;
    }
    for (int i = tid; i < OUT_D * HIDN; i += NTH) sm[W2_OFF + i] = W2[i];
    // zero state region (X + H1 + H2 + H3 + pads)
    for (int i = X_OFF + tid; i < SMEM_FLT; i += NTH) sm[i] = 0.f;
    __syncthreads();
    // x(0) -> X
    if (tid < NB * IN_D) {
        int b = tid / IN_D, k = tid % IN_D;
        sm[X_OFF + (k >> 1) * 8 + 2 * b + (k & 1)] =
            x[((size_t)(b0 + b) * T_LEN) * IN_D + k];
    }
    __syncthreads();

    // ---------------- role setup ----------------
    const int lane = tid & 31, wrp = tid >> 5;
    const bool ishelp = (wrp == 13);
    const int qd = (lane >> 3) & 3;             // column quarter (bits 3,4)
    const int bp = (lane >> 2) & 1;             // batch pair (bit 2)
    const int u_raw = wrp * 4 + (lane & 3);
    const int u = (u_raw < HIDN) ? u_raw : (HIDN - 1);
    const bool dostore = (!ishelp) && (u_raw < HIDN) && (qd == 0);
    const int ob = lane >> 3, oo = lane & 7;    // helper mapping

    const bool full = (wrp < 12);
    const int u2 = full ? (lane & 3) : ((lane & 3) < 1 ? 0 : 1);
    const int blkoff = (u2 * 4 + qd) * 4;
    const int WS = full ? 64 : 32;
    const int GA = full ? 320 : 160;
    const int GB = full ? 448 : 224;
    const float* wa_i = sm + WPA_OFF + (full ? wrp * 1280 : 15360) + blkoff;
    const float* wa_f = wa_i + GA;
    const float* wa_g = wa_i + 2 * GA;
    const float* wa_o = wa_i + 3 * GA;
    const float* wb_i = sm + WPB_OFF + (full ? wrp * 1792 : 21504) + blkoff;
    const float* wb_f = wb_i + GB;
    const float* wb_g = wb_i + 2 * GB;
    const float* wb_o = wb_i + 3 * GB;
    const float* wc_i = sm + WPC_OFF + (full ? wrp * 1344 : 16128) + blkoff;
    const float* wc_g = wc_i + GB;
    const float* wc_o = wc_i + 2 * GB;

    float bai = 0, baf = 0, bag = 0, bao = 0;
    float bbi = 0, bbf = 0, bbg = 0, bbo = 0;
    float bci = 0, bcg = 0, bco = 0, b2r = 0;
    if (!ishelp) {
        bai = bih1[u] + bhh1[u];
        baf = bih1[u + 50] + bhh1[u + 50];
        bag = bih1[u + 100] + bhh1[u + 100];
        bao = bih1[u + 150] + bhh1[u + 150];
        for (int j = 0; j < HIDN; j++) {
            float bj = b1[j];
            bai += Wih1[u * HIDN + j] * bj;
            baf += Wih1[(u + 50) * HIDN + j] * bj;
            bag += Wih1[(u + 100) * HIDN + j] * bj;
            bao += Wih1[(u + 150) * HIDN + j] * bj;
        }
        bbi = bih2[u] + bhh2[u];
        bbf = bih2[u + 50] + bhh2[u + 50];
        bbg = bih2[u + 100] + bhh2[u + 100];
        bbo = bih2[u + 150] + bhh2[u + 150];
        bci = bih3[u] + bhh3[u];
        bcg = bih3[u + 100] + bhh3[u + 100];
        bco = bih3[u + 150] + bhh3[u + 150];
    } else {
        b2r = b2[oo];
    }

    const int up8 = (u >> 1) * 8 + (u & 1);
    const int bpo = 4 * bp;
    // per-qd input bases (qd-dependent but parity added at use)
    const float* in1_x  = sm + X_OFF + bpo;                     // qd==0
    const int    in1_h  = H1_OFF + (qd ? (qd - 1) * 80 : 0) + bpo;
    const int    in2_h1 = H1_OFF + (qd < 2 ? qd * 112 : 0) + bpo;
    const int    in2_h2 = H2_OFF + (qd >= 2 ? (qd - 2) * 112 : 0) + bpo;
    const int    in3_h2 = H2_OFF + (qd < 2 ? qd * 112 : 0) + bpo;
    const int    in3_h3 = H3_OFF + (qd >= 2 ? (qd - 2) * 112 : 0) + bpo;

    float c1s[2] = {0.f, 0.f};
    float czs[2] = {0.f, 0.f};
    float lo, hi;

    // ---------------- prologue: cell1(0) -> h1(0) in H1[0] ----------------
    if (!ishelp) {
        Acc8 A{};
        const float* inp = (qd == 0) ? in1_x : (sm + in1_h + 240);  // h1(-1)=H1[1]=0
        gemv_q<5, true>(wa_i, wa_f, wa_g, wa_o, WS, inp, A);
        CMB4(A)
#pragma unroll
        for (int k = 0; k < 2; k++) {
            ull Ai = k ? A.i1 : A.i0, Af = k ? A.f1 : A.f0;
            ull Ag = k ? A.g1 : A.g0, Ao = k ? A.o1 : A.o0;
            upk(Ai, lo, hi); float iv = sigm(lo + hi + bai);
            upk(Af, lo, hi); float fv = sigm(lo + hi + baf);
            upk(Ag, lo, hi); float gv = tanhap(lo + hi + bag);
            upk(Ao, lo, hi); float ov = sigm(lo + hi + bao);
            c1s[k] = fv * c1s[k] + iv * gv;
            if (dostore)
                sm[H1_OFF + up8 + 2 * (2 * bp + k)] = ov * tanhap(c1s[k]);
        }
    }
    __syncthreads();

    // ---------------- main loop: 2 barriers/step ----------------
    for (int t = 0; t < T_LEN; t++) {
        const int q = t & 1;
        const int qo = q * 240, rqo = (1 - q) * 240;

        // ---- phase alpha: cell2(t) || helper {out(t-1), x(t+1)->X} ----
        if (!ishelp) {
            Acc8 A{};
            const float* inp = sm + ((qd < 2) ? (in2_h1 + qo) : (in2_h2 + rqo));
            gemv_q<7, true>(wb_i, wb_f, wb_g, wb_o, WS, inp, A);
            CMB4(A)
#pragma unroll
            for (int k = 0; k < 2; k++) {
                ull Ai = k ? A.i1 : A.i0, Af = k ? A.f1 : A.f0;
                ull Ag = k ? A.g1 : A.g0, Ao = k ? A.o1 : A.o0;
                upk(Ai, lo, hi); float iv = sigm(lo + hi + bbi);
                upk(Af, lo, hi); float fv = sigm(lo + hi + bbf);
                upk(Ag, lo, hi); float gv = tanhap(lo + hi + bbg);
                upk(Ao, lo, hi); float ov = sigm(lo + hi + bbo);
                float c2t = fv * czs[k] + iv * gv;
                if (dostore)
                    sm[H2_OFF + qo + up8 + 2 * (2 * bp + k)] = ov * tanhap(c2t);
            }
        } else {
            float xv0 = 0.f, xv1 = 0.f, xv2 = 0.f;
            const bool xl = (t + 1 < T_LEN);
            if (xl) {
                { int e = lane;      int b = e / IN_D, k = e % IN_D;
                  xv0 = x[((size_t)(b0 + b) * T_LEN + t + 1) * IN_D + k]; }
                { int e = lane + 32; int b = e / IN_D, k = e % IN_D;
                  xv1 = x[((size_t)(b0 + b) * T_LEN + t + 1) * IN_D + k]; }
                if (lane + 64 < NB * IN_D) {
                  int e = lane + 64; int b = e / IN_D, k = e % IN_D;
                  xv2 = x[((size_t)(b0 + b) * T_LEN + t + 1) * IN_D + k]; }
            }
            if (t > 0) {   // out(t-1): h3(t-1) at H3[1-q]
                const float* h3p = sm + H3_OFF + rqo;
                float acc = b2r;
#pragma unroll
                for (int j = 0; j < HIDN; j++)
                    acc += sm[W2_OFF + oo * HIDN + j] *
                           h3p[(j >> 1) * 8 + 2 * ob + (j & 1)];
                out[((size_t)(b0 + ob) * T_LEN + (t - 1)) * OUT_D + oo] = acc;
            }
            if (xl) {      // x(t+1) -> X (read in phase beta this step)
                { int e = lane;      int b = e / IN_D, k = e % IN_D;
                  sm[X_OFF + (k >> 1) * 8 + 2 * b + (k & 1)] = xv0; }
                { int e = lane + 32; int b = e / IN_D, k = e % IN_D;
                  sm[X_OFF + (k >> 1) * 8 + 2 * b + (k & 1)] = xv1; }
                if (lane + 64 < NB * IN_D) {
                  int e = lane + 64; int b = e / IN_D, k = e % IN_D;
                  sm[X_OFF + (k >> 1) * 8 + 2 * b + (k & 1)] = xv2; }
            }
        }
        __syncthreads();

        // ---- phase beta: cell3(t) + cell1(t+1) (independent, overlap) ----
        if (!ishelp) {
            Acc8 A3{};
            {
                const float* inp = sm + ((qd < 2) ? (in3_h2 + qo) : (in3_h3 + rqo));
                gemv_q<7, false>(wc_i, wc_i, wc_g, wc_o, WS, inp, A3);
            }
            if (t + 1 < T_LEN) {
                Acc8 A1{};
                const float* inp1 = (qd == 0) ? in1_x : (sm + in1_h + qo);
                gemv_q<5, true>(wa_i, wa_f, wa_g, wa_o, WS, inp1, A1);
                CMB3(A3)
#pragma unroll
                for (int k = 0; k < 2; k++) {
                    ull Ai = k ? A3.i1 : A3.i0;
                    ull Ag = k ? A3.g1 : A3.g0, Ao = k ? A3.o1 : A3.o0;
                    upk(Ai, lo, hi); float iv = sigm(lo + hi + bci);
                    upk(Ag, lo, hi); float gv = tanhap(lo + hi + bcg);
                    upk(Ao, lo, hi); float ov = sigm(lo + hi + bco);
                    czs[k] = iv * gv;
                    if (dostore)
                        sm[H3_OFF + qo + up8 + 2 * (2 * bp + k)] = ov * tanhap(czs[k]);
                }
                CMB4(A1)
#pragma unroll
                for (int k = 0; k < 2; k++) {
                    ull Ai = k ? A1.i1 : A1.i0, Af = k ? A1.f1 : A1.f0;
                    ull Ag = k ? A1.g1 : A1.g0, Ao = k ? A1.o1 : A1.o0;
                    upk(Ai, lo, hi); float iv = sigm(lo + hi + bai);
                    upk(Af, lo, hi); float fv = sigm(lo + hi + baf);
                    upk(Ag, lo, hi); float gv = tanhap(lo + hi + bag);
                    upk(Ao, lo, hi); float ov = sigm(lo + hi + bao);
                    c1s[k] = fv * c1s[k] + iv * gv;
                    if (dostore)
                        sm[H1_OFF + rqo + up8 + 2 * (2 * bp + k)] = ov * tanhap(c1s[k]);
                }
            } else {
                CMB3(A3)
#pragma unroll
                for (int k = 0; k < 2; k++) {
                    ull Ai = k ? A3.i1 : A3.i0;
                    ull Ag = k ? A3.g1 : A3.g0, Ao = k ? A3.o1 : A3.o0;
                    upk(Ai, lo, hi); float iv = sigm(lo + hi + bci);
                    upk(Ag, lo, hi); float gv = tanhap(lo + hi + bcg);
                    upk(Ao, lo, hi); float ov = sigm(lo + hi + bco);
                    czs[k] = iv * gv;
                    if (dostore)
                        sm[H3_OFF + qo + up8 + 2 * (2 * bp + k)] = ov * tanhap(czs[k]);
                }
            }
        }
        __syncthreads();
    }

    // epilogue: out(T_LEN-1); h3(T-1) parity 1 -> H3_OFF + 240
    if (ishelp) {
        const float* h3p = sm + H3_OFF + 240;
        float acc = b2r;
#pragma unroll
        for (int j = 0; j < HIDN; j++)
            acc += sm[W2_OFF + oo * HIDN + j] *
                   h3p[(j >> 1) * 8 + 2 * ob + (j & 1)];
        out[((size_t)(b0 + ob) * T_LEN + (T_LEN - 1)) * OUT_D + oo] = acc;
    }
}

extern "C" void kernel_launch(void* const* d_in, const int* in_sizes, int n_in,
                              void* d_out, int out_size)
{
    const float* x    = (const float*)d_in[0];
    const float* W1   = (const float*)d_in[1];
    const float* b1   = (const float*)d_in[2];
    const float* Wih1 = (const float*)d_in[3];
    const float* Whh1 = (const float*)d_in[4];
    const float* bih1 = (const float*)d_in[5];
    const float* bhh1 = (const float*)d_in[6];
    const float* Wih2 = (const float*)d_in[7];
    const float* Whh2 = (const float*)d_in[8];
    const float* bih2 = (const float*)d_in[9];
    const float* bhh2 = (const float*)d_in[10];
    const float* Wih3 = (const float*)d_in[11];
    const float* Whh3 = (const float*)d_in[12];
    const float* bih3 = (const float*)d_in[13];
    const float* bhh3 = (const float*)d_in[14];
    const float* W2   = (const float*)d_in[15];
    const float* b2   = (const float*)d_in[16];
    float* out = (float*)d_out;

    const int smem_bytes = SMEM_FLT * sizeof(float);  // 228,608
    cudaFuncSetAttribute(lstm_persist_kernel,
                         cudaFuncAttributeMaxDynamicSharedMemorySize, smem_bytes);

    lstm_persist_kernel<<<NCTA, NTH, smem_bytes>>>(
        x, W1, b1, Wih1, Whh1, bih1, bhh1,
        Wih2, Whh2, bih2, bhh2, Wih3, Whh3, bih3, bhh3,
        W2, b2, out);
}

// round 15
// speedup vs baseline: 1.7686x; 1.7686x over previous
#include <cuda_runtime.h>

// Net_2095944040841: 3-layer LSTM (reference's buggy c-state wiring) on GB300.
// R13 = R10 (best, 2992us) + (1) beta's cell3(t)/cell1(t+1) gemvs manually
// fused into one interleaved loop (2x MLP in beta), (2) helper's global x-load
// issued one phase early (beta(t-1)) so it never straggles alpha.
// Layout, traffic, and math identical to R10.

#define T_LEN 1024
#define IN_D  20
#define HIDN  50
#define OUT_D 8
#define NB    4
#define NCTA  128
#define NTH   256

// shared memory layout (float offsets)
#define WA_STR 76            // cell1 row: 20 fused-x + 52 h1 cols (+4 pad)
#define WB_STR 108           // cells2/3 row: 52 + 52 cols (+4 pad)
#define WA_OFF 0             // 200 x 76                  -> 15200
#define WB_OFF 15200         // 200 x 108                 -> 36800
#define WC_OFF 36800         // 150 x 108 (i,g,o rows)    -> 53000
#define W2_OFF 53000         // 8 x 50                    -> 53400
#define XH1_OFF 53400        // 2 x 288: [x(80)|h1(208)] per parity -> 53976
#define C2_OFF  53976        // [h1[0]|h2a[1]|h1[1]|h2a[0]] 4x208   -> 54808
#define C3_OFF  54808        // [h2b[0]|h3[1]|h2b[1]|h3[0]] 4x208   -> 55640
#define SMEM_FLT 55640       // 222,560 bytes

typedef unsigned long long ull;

static __device__ __forceinline__ void upk(ull v, float &a, float &b) {
    asm("mov.b64 {%0,%1}, %2;" : "=f"(a), "=f"(b) : "l"(v));
}
static __device__ __forceinline__ ull fma2(ull a, ull b, ull c) {
    ull d; asm("fma.rn.f32x2 %0, %1, %2, %3;" : "=l"(d) : "l"(a), "l"(b), "l"(c)); return d;
}
static __device__ __forceinline__ ull add2(ull a, ull b) {
    ull d; asm("add.rn.f32x2 %0, %1, %2;" : "=l"(d) : "l"(a), "l"(b)); return d;
}
static __device__ __forceinline__ float tanhap(float x) {
    float t; asm("tanh.approx.f32 %0, %1;" : "=f"(t) : "f"(x)); return t;
}
static __device__ __forceinline__ float sigm(float x) {
    return fmaf(tanhap(0.5f * x), 0.5f, 0.5f);
}

struct Acc8 { ull i0, i1, f0, f1, g0, g1, o0, o1; };

// Half-GEMV: NQ chunks (4 cols each) of 4 (or 3) gate rows x 2 batches.
template<int NQ, bool HASF>
static __device__ __forceinline__ void gemv_half(
    const float* __restrict__ wi, const float* __restrict__ wf,
    const float* __restrict__ wg, const float* __restrict__ wo,
    const float* __restrict__ inp, Acc8 &A)
{
#pragma unroll
    for (int kk = 0; kk < NQ; kk++) {
        ulonglong2 qa = *reinterpret_cast<const ulonglong2*>(inp + 16 * kk);
        ulonglong2 qb = *reinterpret_cast<const ulonglong2*>(inp + 16 * kk + 8);
        ulonglong2 wI = *(reinterpret_cast<const ulonglong2*>(wi) + kk);
        ulonglong2 wG = *(reinterpret_cast<const ulonglong2*>(wg) + kk);
        ulonglong2 wO = *(reinterpret_cast<const ulonglong2*>(wo) + kk);
        A.i0 = fma2(wI.x, qa.x, A.i0); A.i1 = fma2(wI.x, qa.y, A.i1);
        A.i0 = fma2(wI.y, qb.x, A.i0); A.i1 = fma2(wI.y, qb.y, A.i1);
        A.g0 = fma2(wG.x, qa.x, A.g0); A.g1 = fma2(wG.x, qa.y, A.g1);
        A.g0 = fma2(wG.y, qb.x, A.g0); A.g1 = fma2(wG.y, qb.y, A.g1);
        A.o0 = fma2(wO.x, qa.x, A.o0); A.o1 = fma2(wO.x, qa.y, A.o1);
        A.o0 = fma2(wO.y, qb.x, A.o0); A.o1 = fma2(wO.y, qb.y, A.o1);
        if (HASF) {
            ulonglong2 wF = *(reinterpret_cast<const ulonglong2*>(wf) + kk);
            A.f0 = fma2(wF.x, qa.x, A.f0); A.f1 = fma2(wF.x, qa.y, A.f1);
            A.f0 = fma2(wF.y, qb.x, A.f0); A.f1 = fma2(wF.y, qb.y, A.f1);
        }
    }
}

#define CMB(a) { ull _o = __shfl_xor_sync(0xffffffffu, a, 16); a = add2(a, _o); }
#define CMB4(A) { CMB(A.i0) CMB(A.i1) CMB(A.f0) CMB(A.f1) CMB(A.g0) CMB(A.g1) CMB(A.o0) CMB(A.o1) }
#define CMB3(A) { CMB(A.i0) CMB(A.i1) CMB(A.g0) CMB(A.g1) CMB(A.o0) CMB(A.o1) }

extern __shared__ float sm[];

__global__ void __launch_bounds__(NTH, 1)
lstm_persist_kernel(const float* __restrict__ x,
                    const float* __restrict__ W1,   const float* __restrict__ b1,
                    const float* __restrict__ Wih1, const float* __restrict__ Whh1,
                    const float* __restrict__ bih1, const float* __restrict__ bhh1,
                    const float* __restrict__ Wih2, const float* __restrict__ Whh2,
                    const float* __restrict__ bih2, const float* __restrict__ bhh2,
                    const float* __restrict__ Wih3, const float* __restrict__ Whh3,
                    const float* __restrict__ bih3, const float* __restrict__ bhh3,
                    const float* __restrict__ W2,   const float* __restrict__ b2,
                    float* __restrict__ out)
{
    const int tid = threadIdx.x;
    const int b0  = blockIdx.x * NB;

    // ---------------- init: weights ----------------
    for (int i = tid; i < HIDN * IN_D; i += NTH) sm[WB_OFF + i] = W1[i];  // stage W1
    __syncthreads();

    for (int i = tid; i < 200 * IN_D; i += NTH) {
        int r = i / IN_D, k = i % IN_D;
        float acc = 0.f;
#pragma unroll 10
        for (int j = 0; j < HIDN; j++)
            acc += Wih1[r * HIDN + j] * sm[WB_OFF + j * IN_D + k];
        sm[WA_OFF + r * WA_STR + k] = acc;
    }
    for (int i = tid; i < 200 * 52; i += NTH) {
        int r = i / 52, c = i % 52;
        sm[WA_OFF + r * WA_STR + IN_D + c] = (c < HIDN) ? Whh1[r * HIDN + c] : 0.f;
    }
    __syncthreads();   // staging reads complete before WB fill

    for (int i = tid; i < 200 * WB_STR; i += NTH) {
        int r = i / WB_STR, c = i % WB_STR;
        float v = 0.f;
        if (c < 52)      { if (c < HIDN) v = Wih2[r * HIDN + c]; }
        else if (c < 104){ int cc = c - 52; if (cc < HIDN) v = Whh2[r * HIDN + cc]; }
        sm[WB_OFF + i] = v;
    }
    for (int i = tid; i < 150 * WB_STR; i += NTH) {
        int rr = i / WB_STR, c = i % WB_STR;
        int src = rr + ((rr < 50) ? 0 : 50);   // live rows: i, g, o
        float v = 0.f;
        if (c < 52)      { if (c < HIDN) v = Wih3[src * HIDN + c]; }
        else if (c < 104){ int cc = c - 52; if (cc < HIDN) v = Whh3[src * HIDN + cc]; }
        sm[WC_OFF + i] = v;
    }
    for (int i = tid; i < OUT_D * HIDN; i += NTH) sm[W2_OFF + i] = W2[i];

    for (int i = tid; i < SMEM_FLT - XH1_OFF; i += NTH) sm[XH1_OFF + i] = 0.f;
    __syncthreads();
    // x(0) into XH1 parity 1 x-part (prologue reads parity 1)
    if (tid < NB * IN_D) {
        int b = tid / IN_D, k = tid % IN_D;
        sm[XH1_OFF + 288 + (k >> 1) * 8 + 2 * b + (k & 1)] =
            x[((size_t)(b0 + b) * T_LEN) * IN_D + k];
    }
    __syncthreads();

    // ---------------- role setup ----------------
    const int lane = tid & 31, wrp = tid >> 5;
    const bool ishelp = (wrp == 7);
    const int half = lane >> 4;
    const int bp   = (lane >> 3) & 1;
    const int u_raw = wrp * 8 + (lane & 7);
    const int u = (u_raw < HIDN) ? u_raw : (HIDN - 1);
    const bool dostore = (!ishelp) && (u_raw < HIDN) && (half == 0);
    const int ob = lane >> 3, oo = lane & 7;

    const float* wa_i = sm + WA_OFF + u * WA_STR + half * 36;
    const float* wa_f = wa_i + 50 * WA_STR;
    const float* wa_g = wa_i + 100 * WA_STR;
    const float* wa_o = wa_i + 150 * WA_STR;
    const float* wb_i = sm + WB_OFF + u * WB_STR + half * 52;
    const float* wb_f = wb_i + 50 * WB_STR;
    const float* wb_g = wb_i + 100 * WB_STR;
    const float* wb_o = wb_i + 150 * WB_STR;
    const float* wc_i = sm + WC_OFF + u * WB_STR + half * 52;
    const float* wc_g = wc_i + 50 * WB_STR;
    const float* wc_o = wc_i + 100 * WB_STR;

    float bai = 0, baf = 0, bag = 0, bao = 0;
    float bbi = 0, bbf = 0, bbg = 0, bbo = 0;
    float bci = 0, bcg = 0, bco = 0, b2r = 0;
    if (!ishelp) {
        bai = bih1[u] + bhh1[u];
        baf = bih1[u + 50] + bhh1[u + 50];
        bag = bih1[u + 100] + bhh1[u + 100];
        bao = bih1[u + 150] + bhh1[u + 150];
        for (int j = 0; j < HIDN; j++) {
            float bj = b1[j];
            bai += Wih1[u * HIDN + j] * bj;
            baf += Wih1[(u + 50) * HIDN + j] * bj;
            bag += Wih1[(u + 100) * HIDN + j] * bj;
            bao += Wih1[(u + 150) * HIDN + j] * bj;
        }
        bbi = bih2[u] + bhh2[u];
        bbf = bih2[u + 50] + bhh2[u + 50];
        bbg = bih2[u + 100] + bhh2[u + 100];
        bbo = bih2[u + 150] + bhh2[u + 150];
        bci = bih3[u] + bhh3[u];
        bcg = bih3[u + 100] + bhh3[u + 100];
        bco = bih3[u + 150] + bhh3[u + 150];
    } else {
        b2r = b2[oo];
    }

    const int up8 = (u >> 1) * 8 + (u & 1);
    const int bpo = 4 * bp;
    float c1s[2] = {0.f, 0.f};
    float czs[2] = {0.f, 0.f};
    float lo, hi;
    float xv0 = 0.f, xv1 = 0.f, xv2 = 0.f;   // helper's in-flight x values

    // ---------------- prologue: cell1(0) || helper loads x(1) ----------------
    if (!ishelp) {
        Acc8 A{};
        gemv_half<9, true>(wa_i, wa_f, wa_g, wa_o,
                           sm + XH1_OFF + 288 + half * 144 + bpo, A);
        CMB4(A)
#pragma unroll
        for (int k = 0; k < 2; k++) {
            ull Ai = k ? A.i1 : A.i0, Af = k ? A.f1 : A.f0;
            ull Ag = k ? A.g1 : A.g0, Ao = k ? A.o1 : A.o0;
            upk(Ai, lo, hi); float iv = sigm(lo + hi + bai);
            upk(Af, lo, hi); float fv = sigm(lo + hi + baf);
            upk(Ag, lo, hi); float gv = tanhap(lo + hi + bag);
            upk(Ao, lo, hi); float ov = sigm(lo + hi + bao);
            c1s[k] = fv * c1s[k] + iv * gv;
            float h = ov * tanhap(c1s[k]);
            if (dostore) {
                int b = 2 * bp + k;
                sm[XH1_OFF + 80 + up8 + 2 * b] = h;     // XH1[0].h1
                sm[C2_OFF + up8 + 2 * b] = h;           // C2 h1[0]
            }
        }
    } else {
        // load x(1) (stored in alpha(0))
        { int e = lane;      int b = e / IN_D, k = e % IN_D;
          xv0 = x[((size_t)(b0 + b) * T_LEN + 1) * IN_D + k]; }
        { int e = lane + 32; int b = e / IN_D, k = e % IN_D;
          xv1 = x[((size_t)(b0 + b) * T_LEN + 1) * IN_D + k]; }
        if (lane + 64 < NB * IN_D) {
          int e = lane + 64; int b = e / IN_D, k = e % IN_D;
          xv2 = x[((size_t)(b0 + b) * T_LEN + 1) * IN_D + k]; }
    }
    __syncthreads();

    // ---------------- main loop: 2 barriers/step ----------------
    for (int t = 0; t < T_LEN; t++) {
        const int q = t & 1;

        // ---- phase alpha: cell2(t) || helper {store x(t+1), out(t-1)} ----
        if (!ishelp) {
            Acc8 A{};
            gemv_half<13, true>(wb_i, wb_f, wb_g, wb_o,
                                sm + C2_OFF + q * 416 + half * 208 + bpo, A);
            CMB4(A)
#pragma unroll
            for (int k = 0; k < 2; k++) {
                ull Ai = k ? A.i1 : A.i0, Af = k ? A.f1 : A.f0;
                ull Ag = k ? A.g1 : A.g0, Ao = k ? A.o1 : A.o0;
                upk(Ai, lo, hi); float iv = sigm(lo + hi + bbi);
                upk(Af, lo, hi); float fv = sigm(lo + hi + bbf);
                upk(Ag, lo, hi); float gv = tanhap(lo + hi + bbg);
                upk(Ao, lo, hi); float ov = sigm(lo + hi + bbo);
                float c2t = fv * czs[k] + iv * gv;
                float h = ov * tanhap(c2t);
                if (dostore) {
                    int b = 2 * bp + k;
                    sm[C2_OFF + 208 + (1 - q) * 416 + up8 + 2 * b] = h;  // h2a[q]
                    sm[C3_OFF + q * 416 + up8 + 2 * b] = h;              // h2b[q]
                }
            }
        } else {
            if (t + 1 < T_LEN) {   // store x(t+1) (loaded last phase) -> XH1[q].x
                { int e = lane;      int b = e / IN_D, k = e % IN_D;
                  sm[XH1_OFF + q * 288 + (k >> 1) * 8 + 2 * b + (k & 1)] = xv0; }
                { int e = lane + 32; int b = e / IN_D, k = e % IN_D;
                  sm[XH1_OFF + q * 288 + (k >> 1) * 8 + 2 * b + (k & 1)] = xv1; }
                if (lane + 64 < NB * IN_D) {
                  int e = lane + 64; int b = e / IN_D, k = e % IN_D;
                  sm[XH1_OFF + q * 288 + (k >> 1) * 8 + 2 * b + (k & 1)] = xv2; }
            }
            if (t > 0) {   // out(t-1): h3 parity (1-q) at C3+208+q*416
                const float* h3p = sm + C3_OFF + 208 + q * 416;
                float acc = b2r;
#pragma unroll
                for (int j = 0; j < HIDN; j++)
                    acc += sm[W2_OFF + oo * HIDN + j] *
                           h3p[(j >> 1) * 8 + 2 * ob + (j & 1)];
                out[((size_t)(b0 + ob) * T_LEN + (t - 1)) * OUT_D + oo] = acc;
            }
        }
        __syncthreads();

        // ---- phase beta: FUSED cell3(t) + cell1(t+1) || helper loads x(t+2) ----
        if (!ishelp) {
            if (t + 1 < T_LEN) {
                Acc8 A3{};
                Acc8 A1{};
                const float* in3 = sm + C3_OFF + q * 416 + half * 208 + bpo;
                const float* in1 = sm + XH1_OFF + q * 288 + half * 144 + bpo;
#pragma unroll
                for (int kk = 0; kk < 13; kk++) {
                    ulonglong2 qa = *reinterpret_cast<const ulonglong2*>(in3 + 16 * kk);
                    ulonglong2 qb = *reinterpret_cast<const ulonglong2*>(in3 + 16 * kk + 8);
                    ulonglong2 wI = *(reinterpret_cast<const ulonglong2*>(wc_i) + kk);
                    ulonglong2 wG = *(reinterpret_cast<const ulonglong2*>(wc_g) + kk);
                    ulonglong2 wO = *(reinterpret_cast<const ulonglong2*>(wc_o) + kk);
                    A3.i0 = fma2(wI.x, qa.x, A3.i0); A3.i1 = fma2(wI.x, qa.y, A3.i1);
                    A3.i0 = fma2(wI.y, qb.x, A3.i0); A3.i1 = fma2(wI.y, qb.y, A3.i1);
                    A3.g0 = fma2(wG.x, qa.x, A3.g0); A3.g1 = fma2(wG.x, qa.y, A3.g1);
                    A3.g0 = fma2(wG.y, qb.x, A3.g0); A3.g1 = fma2(wG.y, qb.y, A3.g1);
                    A3.o0 = fma2(wO.x, qa.x, A3.o0); A3.o1 = fma2(wO.x, qa.y, A3.o1);
                    A3.o0 = fma2(wO.y, qb.x, A3.o0); A3.o1 = fma2(wO.y, qb.y, A3.o1);
                    if (kk < 9) {
                        ulonglong2 pa = *reinterpret_cast<const ulonglong2*>(in1 + 16 * kk);
                        ulonglong2 pb = *reinterpret_cast<const ulonglong2*>(in1 + 16 * kk + 8);
                        ulonglong2 vI = *(reinterpret_cast<const ulonglong2*>(wa_i) + kk);
                        ulonglong2 vF = *(reinterpret_cast<const ulonglong2*>(wa_f) + kk);
                        ulonglong2 vG = *(reinterpret_cast<const ulonglong2*>(wa_g) + kk);
                        ulonglong2 vO = *(reinterpret_cast<const ulonglong2*>(wa_o) + kk);
                        A1.i0 = fma2(vI.x, pa.x, A1.i0); A1.i1 = fma2(vI.x, pa.y, A1.i1);
                        A1.i0 = fma2(vI.y, pb.x, A1.i0); A1.i1 = fma2(vI.y, pb.y, A1.i1);
                        A1.f0 = fma2(vF.x, pa.x, A1.f0); A1.f1 = fma2(vF.x, pa.y, A1.f1);
                        A1.f0 = fma2(vF.y, pb.x, A1.f0); A1.f1 = fma2(vF.y, pb.y, A1.f1);
                        A1.g0 = fma2(vG.x, pa.x, A1.g0); A1.g1 = fma2(vG.x, pa.y, A1.g1);
                        A1.g0 = fma2(vG.y, pb.x, A1.g0); A1.g1 = fma2(vG.y, pb.y, A1.g1);
                        A1.o0 = fma2(vO.x, pa.x, A1.o0); A1.o1 = fma2(vO.x, pa.y, A1.o1);
                        A1.o0 = fma2(vO.y, pb.x, A1.o0); A1.o1 = fma2(vO.y, pb.y, A1.o1);
                    }
                }
                CMB3(A3)
#pragma unroll
                for (int k = 0; k < 2; k++) {
                    ull Ai = k ? A3.i1 : A3.i0;
                    ull Ag = k ? A3.g1 : A3.g0, Ao = k ? A3.o1 : A3.o0;
                    upk(Ai, lo, hi); float iv = sigm(lo + hi + bci);
                    upk(Ag, lo, hi); float gv = tanhap(lo + hi + bcg);
                    upk(Ao, lo, hi); float ov = sigm(lo + hi + bco);
                    czs[k] = iv * gv;
                    float h = ov * tanhap(czs[k]);
                    if (dostore)
                        sm[C3_OFF + 208 + (1 - q) * 416 + up8 + 2 * (2 * bp + k)] = h;
                }
                CMB4(A1)
#pragma unroll
                for (int k = 0; k < 2; k++) {
                    ull Ai = k ? A1.i1 : A1.i0, Af = k ? A1.f1 : A1.f0;
                    ull Ag = k ? A1.g1 : A1.g0, Ao = k ? A1.o1 : A1.o0;
                    upk(Ai, lo, hi); float iv = sigm(lo + hi + bai);
                    upk(Af, lo, hi); float fv = sigm(lo + hi + baf);
                    upk(Ag, lo, hi); float gv = tanhap(lo + hi + bag);
                    upk(Ao, lo, hi); float ov = sigm(lo + hi + bao);
                    c1s[k] = fv * c1s[k] + iv * gv;
                    float h = ov * tanhap(c1s[k]);
                    if (dostore) {
                        int b = 2 * bp + k;
                        sm[XH1_OFF + (1 - q) * 288 + 80 + up8 + 2 * b] = h;
                        sm[C2_OFF + (1 - q) * 416 + up8 + 2 * b] = h;
                    }
                }
            } else {
                Acc8 A3{};
                gemv_half<13, false>(wc_i, wc_i, wc_g, wc_o,
                                     sm + C3_OFF + q * 416 + half * 208 + bpo, A3);
                CMB3(A3)
#pragma unroll
                for (int k = 0; k < 2; k++) {
                    ull Ai = k ? A3.i1 : A3.i0;
                    ull Ag = k ? A3.g1 : A3.g0, Ao = k ? A3.o1 : A3.o0;
                    upk(Ai, lo, hi); float iv = sigm(lo + hi + bci);
                    upk(Ag, lo, hi); float gv = tanhap(lo + hi + bcg);
                    upk(Ao, lo, hi); float ov = sigm(lo + hi + bco);
                    czs[k] = iv * gv;
                    float h = ov * tanhap(czs[k]);
                    if (dostore)
                        sm[C3_OFF + 208 + (1 - q) * 416 + up8 + 2 * (2 * bp + k)] = h;
                }
            }
        } else {
            if (t + 2 < T_LEN) {   // load x(t+2); stored in alpha(t+1)
                { int e = lane;      int b = e / IN_D, k = e % IN_D;
                  xv0 = x[((size_t)(b0 + b) * T_LEN + t + 2) * IN_D + k]; }
                { int e = lane + 32; int b = e / IN_D, k = e % IN_D;
                  xv1 = x[((size_t)(b0 + b) * T_LEN + t + 2) * IN_D + k]; }
                if (lane + 64 < NB * IN_D) {
                  int e = lane + 64; int b = e / IN_D, k = e % IN_D;
                  xv2 = x[((size_t)(b0 + b) * T_LEN + t + 2) * IN_D + k]; }
            }
        }
        __syncthreads();
    }

    // epilogue: out(T_LEN-1); h3 parity 1 at C3+208+0*416
    if (ishelp) {
        const float* h3p = sm + C3_OFF + 208;
        float acc = b2r;
#pragma unroll
        for (int j = 0; j < HIDN; j++)
            acc += sm[W2_OFF + oo * HIDN + j] *
                   h3p[(j >> 1) * 8 + 2 * ob + (j & 1)];
        out[((size_t)(b0 + ob) * T_LEN + (T_LEN - 1)) * OUT_D + oo] = acc;
    }
}

extern "C" void kernel_launch(void* const* d_in, const int* in_sizes, int n_in,
                              void* d_out, int out_size)
{
    const float* x    = (const float*)d_in[0];
    const float* W1   = (const float*)d_in[1];
    const float* b1   = (const float*)d_in[2];
    const float* Wih1 = (const float*)d_in[3];
    const float* Whh1 = (const float*)d_in[4];
    const float* bih1 = (const float*)d_in[5];
    const float* bhh1 = (const float*)d_in[6];
    const float* Wih2 = (const float*)d_in[7];
    const float* Whh2 = (const float*)d_in[8];
    const float* bih2 = (const float*)d_in[9];
    const float* bhh2 = (const float*)d_in[10];
    const float* Wih3 = (const float*)d_in[11];
    const float* Whh3 = (const float*)d_in[12];
    const float* bih3 = (const float*)d_in[13];
    const float* bhh3 = (const float*)d_in[14];
    const float* W2   = (const float*)d_in[15];
    const float* b2   = (const float*)d_in[16];
    float* out = (float*)d_out;

    const int smem_bytes = SMEM_FLT * sizeof(float);  // 222,560
    cudaFuncSetAttribute(lstm_persist_kernel,
                         cudaFuncAttributeMaxDynamicSharedMemorySize, smem_bytes);

    lstm_persist_kernel<<<NCTA, NTH, smem_bytes>>>(
        x, W1, b1, Wih1, Whh1, bih1, bhh1,
        Wih2, Whh2, bih2, bhh2, Wih3, Whh3, bih3, bhh3,
        W2, b2, out);
}